// round 15
// baseline (speedup 1.0000x reference)
#include <cuda_runtime.h>
#include <cuda_fp16.h>
#include <cstdint>

#define NB   8
#define HW   2304
#define DD   1024
#define NROW (NB * HW)

// ------------------------------ scratch ------------------------------------
__device__ __half g_fa[(size_t)NROW * DD];    // normalized A, x10 = 1/TEMP
__device__ __half g_fb[(size_t)NROW * DD];    // normalized B
__device__ __half g_posT[(size_t)DD * HW];    // pos emb transposed [D][HW]
__device__ __half g_expv[(size_t)NROW * HW];  // UNNORMALIZED exp(logits), fp16
__device__ float  g_rowpart[(size_t)NROW * 9];// per-(row, bn-tile) exp partial sums
__device__ float  g_inv[NROW];                // 1 / rowsum

// ------------------------------ helpers ------------------------------------
__device__ __forceinline__ uint32_t smem_u32(const void* p) {
    uint32_t a;
    asm("{ .reg .u64 t; cvta.to.shared.u64 t, %1; cvt.u32.u64 %0, t; }" : "=r"(a) : "l"(p));
    return a;
}
__device__ __forceinline__ void cpa16(uint32_t dst, const void* src) {
    asm volatile("cp.async.cg.shared.global [%0], [%1], 16;" :: "r"(dst), "l"(src));
}
__device__ __forceinline__ void cpa_commit() {
    asm volatile("cp.async.commit_group;" ::: "memory");
}
__device__ __forceinline__ void cpa_wait2() {
    asm volatile("cp.async.wait_group 2;" ::: "memory");
}
__device__ __forceinline__ void cpa_wait1() {
    asm volatile("cp.async.wait_group 1;" ::: "memory");
}
__device__ __forceinline__ void cpa_wait0() {
    asm volatile("cp.async.wait_group 0;" ::: "memory");
}
__device__ __forceinline__ void ldsm_x4(uint32_t* r, uint32_t addr) {
    asm volatile("ldmatrix.sync.aligned.m8n8.x4.shared.b16 {%0,%1,%2,%3}, [%4];"
                 : "=r"(r[0]), "=r"(r[1]), "=r"(r[2]), "=r"(r[3]) : "r"(addr));
}
// D += A * B^T via m16n8k16 fp16 inputs, fp32 accum (row.col)
__device__ __forceinline__ void mma_f16(float* c, const uint32_t* a, const uint32_t* b) {
    asm volatile(
        "mma.sync.aligned.m16n8k16.row.col.f32.f16.f16.f32 "
        "{%0,%1,%2,%3}, {%4,%5,%6,%7}, {%8,%9}, {%0,%1,%2,%3};"
        : "+f"(c[0]), "+f"(c[1]), "+f"(c[2]), "+f"(c[3])
        : "r"(a[0]), "r"(a[1]), "r"(a[2]), "r"(a[3]), "r"(b[0]), "r"(b[1]));
}

// ---------------------------------------------------------------------------
// Row L2-normalization -> fp16 scratch. grid=(NROW,2), block=256.
// ---------------------------------------------------------------------------
__global__ __launch_bounds__(256) void normalize_kernel(
    const float* __restrict__ A, const float* __restrict__ Bm)
{
    const int row   = blockIdx.x;
    const int which = blockIdx.y;
    const float* src = which ? Bm : A;
    __half*      dst = which ? g_fb : g_fa;
    const size_t base = (size_t)row * DD;

    float4 v = ((const float4*)(src + base))[threadIdx.x];
    float ss = v.x * v.x + v.y * v.y + v.z * v.z + v.w * v.w;
    #pragma unroll
    for (int o = 16; o; o >>= 1) ss += __shfl_xor_sync(0xffffffffu, ss, o);

    __shared__ float ws[8];
    if ((threadIdx.x & 31) == 0) ws[threadIdx.x >> 5] = ss;
    __syncthreads();
    float tot = 0.f;
    #pragma unroll
    for (int i = 0; i < 8; i++) tot += ws[i];

    const float inv = rsqrtf(tot) * (which ? 1.0f : 10.0f);
    __half2 h0 = __floats2half2_rn(v.x * inv, v.y * inv);
    __half2 h1 = __floats2half2_rn(v.z * inv, v.w * inv);
    uint2 pack = make_uint2(*(uint32_t*)&h0, *(uint32_t*)&h1);
    ((uint2*)(dst + base))[threadIdx.x] = pack;
}

// ---------------------------------------------------------------------------
// Fourier pos-emb TRANSPOSED: g_posT[d][p], fp16. grid=512 (omega rows).
// ---------------------------------------------------------------------------
__global__ __launch_bounds__(256) void posemb_kernel(
    const float* __restrict__ omega, const float* __restrict__ scale)
{
    const int k = blockIdx.x;                  // 0..511
    const float2 om = ((const float2*)omega)[k];
    const float s  = *scale;
    __half* rsin = g_posT + (size_t)k * HW;
    __half* rcos = g_posT + (size_t)(512 + k) * HW;

    for (int p = threadIdx.x; p < HW; p += 256) {
        const int i = p / 48, j = p % 48;
        const float gy = -1.0f + 2.0f * (float)i / 47.0f;
        const float gx = -1.0f + 2.0f * (float)j / 47.0f;
        float sn, cs;
        sincosf(s * (gx * om.x + gy * om.y), &sn, &cs);
        rsin[p] = __float2half_rn(sn);
        rcos[p] = __float2half_rn(cs);
    }
}

// ---------------------------------------------------------------------------
// fp16 mma.sync GEMM: C[M,N](f32) = A[M,K] * B[N,K]^T, batched on blockIdx.z.
// Block tile 128x256, warp tile 64x64 (8 warps, 2x4), BK=32 halves,
// 4-stage cp.async (3-ahead), ldmatrix + register double-buffering.
// EPI=0: plain store. EPI=1 (GEMM1): also store exp(acc) fp16 to g_expv and
// deterministic per-row partial sums. EPI=2 (GEMM2): scale rows by g_inv.
// ---------------------------------------------------------------------------
#define BM 128
#define BN 256
#define BK 32
#define PADK 40                          // halves; 80B row stride, conflict-free
#define STAGE_BYTES ((BM + BN) * PADK * 2)   // 30720 B
#define NSTG 4

extern __shared__ __half smh[];

template<int EPI>
__global__ __launch_bounds__(256, 1)
void gemm_f16_kernel(const __half* __restrict__ A, const __half* __restrict__ B,
                     float* __restrict__ C,
                     int K, int lda, int ldb, int ldc,
                     size_t sA, size_t sB, size_t sC)
{
    const uint32_t sbase = smem_u32(smh);
    const int tid  = threadIdx.x;
    const int wid  = tid >> 5;
    const int lane = tid & 31;
    const int bm = blockIdx.y * BM;
    const int bn = blockIdx.x * BN;

    A += (size_t)blockIdx.z * sA;
    B += (size_t)blockIdx.z * sB;
    C += (size_t)blockIdx.z * sC;

    // ---- loader: thread owns row lr (A: 1 row, B: 2 rows), 32B (2x16B) ----
    const int lr = tid >> 1;           // 0..127
    const int lc = (tid & 1) * 16;     // halves offset: 0 or 16
    const __half* pa  = A + (size_t)(bm + lr) * lda + lc;
    const __half* pb0 = B + (size_t)(bn + lr) * ldb + lc;
    const __half* pb1 = pb0 + (size_t)128 * ldb;
    const uint32_t daa = sbase + (uint32_t)(lr * PADK + lc) * 2;
    const uint32_t db0 = sbase + BM * PADK * 2 + (uint32_t)(lr * PADK + lc) * 2;
    const uint32_t db1 = db0 + 128 * PADK * 2;

    const int nkt = K / BK;

    #define ISSUE(kt, s) do {                                     \
        const uint32_t o = (uint32_t)(s) * STAGE_BYTES;           \
        const int off = (kt) * BK;                                \
        cpa16(daa + o,      pa  + off);                           \
        cpa16(daa + o + 16, pa  + off + 8);                       \
        cpa16(db0 + o,      pb0 + off);                           \
        cpa16(db0 + o + 16, pb0 + off + 8);                       \
        cpa16(db1 + o,      pb1 + off);                           \
        cpa16(db1 + o + 16, pb1 + off + 8);                       \
        cpa_commit();                                             \
    } while (0)

    ISSUE(0, 0);
    ISSUE(1, 1);
    ISSUE(2, 2);

    // ---- compute addressing (ldmatrix lane layout) ----
    const int wm   = (wid & 1) * 64;   // warp M offset (2 rows of warps)
    const int wn   = (wid >> 1) * 64;  // warp N offset (4 cols of warps)
    const int lrow = lane & 7;
    const int msel = lane >> 3;        // matrix select 0..3
    const uint32_t aoff0 = (uint32_t)(((wm + (msel & 1) * 8 + lrow) * PADK + (msel >> 1) * 8) * 2);
    const uint32_t boff0 = (uint32_t)(((wn + (msel >> 1) * 8 + lrow) * PADK + (msel & 1) * 8) * 2)
                         + BM * PADK * 2;
    const int ga  = lane >> 2;
    const int tig = lane & 3;

    float acc[4][8][4];
    #pragma unroll
    for (int i = 0; i < 4; i++)
        #pragma unroll
        for (int j = 0; j < 8; j++)
            #pragma unroll
            for (int q = 0; q < 4; q++) acc[i][j][q] = 0.f;

    uint32_t af[2][4][4];   // [buf][am][4]
    uint32_t bf[2][4][4];   // [buf][jb][4]

    for (int kt = 0; kt < nkt; kt++) {
        const uint32_t stA = sbase + (uint32_t)(kt % NSTG) * STAGE_BYTES;
        if (kt + 2 < nkt)      cpa_wait2();
        else if (kt + 1 < nkt) cpa_wait1();
        else                   cpa_wait0();
        __syncthreads();

        // prime kk=0 fragments FIRST (MMAs start ASAP), then issue next stage
        #pragma unroll
        for (int am = 0; am < 4; am++)
            ldsm_x4(af[0][am], stA + aoff0 + am * (16 * PADK * 2));
        #pragma unroll
        for (int jb = 0; jb < 4; jb++)
            ldsm_x4(bf[0][jb], stA + boff0 + jb * (16 * PADK * 2));

        if (kt + 3 < nkt) ISSUE(kt + 3, (kt + 3) % NSTG);

        #pragma unroll
        for (int kk = 0; kk < 2; kk++) {       // BK=32 -> 2 x k16
            const int cur = kk & 1, nxt = cur ^ 1;
            if (kk < 1) {
                const uint32_t kkb = 32;       // 16 halves = 32 B
                #pragma unroll
                for (int am = 0; am < 4; am++)
                    ldsm_x4(af[nxt][am], stA + aoff0 + am * (16 * PADK * 2) + kkb);
                #pragma unroll
                for (int jb = 0; jb < 4; jb++)
                    ldsm_x4(bf[nxt][jb], stA + boff0 + jb * (16 * PADK * 2) + kkb);
            }
            #pragma unroll
            for (int am = 0; am < 4; am++) {
                #pragma unroll
                for (int jb = 0; jb < 4; jb++) {
                    mma_f16(acc[am][2 * jb],     af[cur][am], &bf[cur][jb][0]);
                    mma_f16(acc[am][2 * jb + 1], af[cur][am], &bf[cur][jb][2]);
                }
            }
        }
    }

    // ---- epilogue ----
    __shared__ float rs[128][4];   // per-local-row exp partials across 4 warp-cols

    if (EPI == 1) {
        __half* ev = g_expv + (size_t)blockIdx.z * HW * HW;
        const int wnx = wid >> 1;   // warp column 0..3
        #pragma unroll
        for (int am = 0; am < 4; am++) {
            const int row = bm + wm + am * 16 + ga;
            float rsl = 0.f, rsh = 0.f;
            #pragma unroll
            for (int an = 0; an < 8; an++) {
                const int col = bn + wn + an * 8 + tig * 2;
                const float a0 = acc[am][an][0], a1 = acc[am][an][1];
                const float a2 = acc[am][an][2], a3 = acc[am][an][3];
                *(float2*)(C + (size_t)row * ldc + col)       = make_float2(a0, a1);
                *(float2*)(C + (size_t)(row + 8) * ldc + col) = make_float2(a2, a3);
                const float e0 = __expf(a0), e1 = __expf(a1);
                const float e2 = __expf(a2), e3 = __expf(a3);
                *(__half2*)(ev + (size_t)row * HW + col)       = __floats2half2_rn(e0, e1);
                *(__half2*)(ev + (size_t)(row + 8) * HW + col) = __floats2half2_rn(e2, e3);
                rsl += e0 + e1;
                rsh += e2 + e3;
            }
            rsl += __shfl_xor_sync(0xffffffffu, rsl, 1);
            rsl += __shfl_xor_sync(0xffffffffu, rsl, 2);
            rsh += __shfl_xor_sync(0xffffffffu, rsh, 1);
            rsh += __shfl_xor_sync(0xffffffffu, rsh, 2);
            if (tig == 0) {
                rs[wm + am * 16 + ga][wnx]     = rsl;
                rs[wm + am * 16 + ga + 8][wnx] = rsh;
            }
        }
        __syncthreads();
        if (tid < 128) {
            const float s = rs[tid][0] + rs[tid][1] + rs[tid][2] + rs[tid][3];
            g_rowpart[((size_t)blockIdx.z * HW + bm + tid) * 9 + blockIdx.x] = s;
        }
    } else if (EPI == 2) {
        const float* iv = g_inv + (size_t)blockIdx.z * HW;
        #pragma unroll
        for (int am = 0; am < 4; am++) {
            const int row = bm + wm + am * 16 + ga;
            const float il = iv[row];
            const float ih = iv[row + 8];
            #pragma unroll
            for (int an = 0; an < 8; an++) {
                const int col = bn + wn + an * 8 + tig * 2;
                *(float2*)(C + (size_t)row * ldc + col) =
                    make_float2(acc[am][an][0] * il, acc[am][an][1] * il);
                *(float2*)(C + (size_t)(row + 8) * ldc + col) =
                    make_float2(acc[am][an][2] * ih, acc[am][an][3] * ih);
            }
        }
    } else {
        #pragma unroll
        for (int am = 0; am < 4; am++) {
            const int row = bm + wm + am * 16 + ga;
            #pragma unroll
            for (int an = 0; an < 8; an++) {
                const int col = bn + wn + an * 8 + tig * 2;
                *(float2*)(C + (size_t)row * ldc + col) =
                    make_float2(acc[am][an][0], acc[am][an][1]);
                *(float2*)(C + (size_t)(row + 8) * ldc + col) =
                    make_float2(acc[am][an][2], acc[am][an][3]);
            }
        }
    }
    #undef ISSUE
}

// ---------------------------------------------------------------------------
// Scale kernel: S_q = sum of 9 deterministic partials; attn = expv * (1/S).
// Also stores 1/S for GEMM2's epilogue. 1 block/row, 256 threads.
// ---------------------------------------------------------------------------
__global__ __launch_bounds__(256) void scale_kernel(float* __restrict__ attn)
{
    const size_t row = blockIdx.x;
    float S = 0.f;
    #pragma unroll
    for (int i = 0; i < 9; i++) S += g_rowpart[row * 9 + i];
    const float inv = 1.0f / S;
    if (threadIdx.x == 0) g_inv[row] = inv;

    const uint2* ev = (const uint2*)(g_expv + row * HW);
    float4* dst = (float4*)(attn + row * HW);
    for (int i = threadIdx.x; i < HW / 4; i += 256) {
        const uint2 p = ev[i];
        const __half2 h0 = *(const __half2*)&p.x;
        const __half2 h1 = *(const __half2*)&p.y;
        const float2 f0 = __half22float2(h0);
        const float2 f1 = __half22float2(h1);
        dst[i] = make_float4(f0.x * inv, f0.y * inv, f1.x * inv, f1.y * inv);
    }
}

// ---------------------------------------------------------------------------
extern "C" void kernel_launch(void* const* d_in, const int* in_sizes, int n_in,
                              void* d_out, int out_size)
{
    const float* fA    = (const float*)d_in[0];
    const float* fB    = (const float*)d_in[1];
    const float* omega = (const float*)d_in[2];
    const float* scale = (const float*)d_in[3];

    float* out    = (float*)d_out;
    float* logits = out;
    float* attn   = out + (size_t)NB * HW * HW;
    float* match  = attn + (size_t)NB * HW * HW;

    __half *fa_p, *fb_p, *pos_p, *ex_p;
    cudaGetSymbolAddress((void**)&fa_p,  g_fa);
    cudaGetSymbolAddress((void**)&fb_p,  g_fb);
    cudaGetSymbolAddress((void**)&pos_p, g_posT);
    cudaGetSymbolAddress((void**)&ex_p,  g_expv);

    const int smem_bytes = NSTG * STAGE_BYTES;   // 122880
    static bool attr_set = false;
    if (!attr_set) {
        cudaFuncSetAttribute(gemm_f16_kernel<1>,
                             cudaFuncAttributeMaxDynamicSharedMemorySize, smem_bytes);
        cudaFuncSetAttribute(gemm_f16_kernel<2>,
                             cudaFuncAttributeMaxDynamicSharedMemorySize, smem_bytes);
        attr_set = true;
    }

    normalize_kernel<<<dim3(NROW, 2), 256>>>(fA, fB);
    posemb_kernel<<<512, 256>>>(omega, scale);

    // GEMM1: logits[b] = fa[b] @ fb[b]^T; epilogue: exp + partial row sums
    gemm_f16_kernel<1><<<dim3(HW / BN, HW / BM, NB), 256, smem_bytes>>>(
        fa_p, fb_p, logits, DD, DD, DD, HW,
        (size_t)HW * DD, (size_t)HW * DD, (size_t)HW * HW);

    // attn = expv / S  (also records 1/S for GEMM2)
    scale_kernel<<<NROW, 256>>>(attn);

    // GEMM2: match[b] = (expv[b] @ posT^T) * inv_q  (softmax factored out)
    gemm_f16_kernel<2><<<dim3(DD / BN, HW / BM, NB), 256, smem_bytes>>>(
        ex_p, pos_p, match, HW, HW, HW, DD,
        (size_t)HW * HW, (size_t)0, (size_t)HW * DD);
}

// round 16
// speedup vs baseline: 1.0314x; 1.0314x over previous
#include <cuda_runtime.h>
#include <cuda_fp16.h>
#include <cstdint>

#define NB   8
#define HW   2304
#define DD   1024
#define NROW (NB * HW)

// ------------------------------ scratch ------------------------------------
__device__ __half g_fa[(size_t)NROW * DD];    // normalized A, x10 = 1/TEMP
__device__ __half g_fb[(size_t)NROW * DD];    // normalized B
__device__ __half g_posT[(size_t)DD * HW];    // pos emb transposed [D][HW]
__device__ __half g_attnh[(size_t)NROW * HW]; // fp16 copy of attn for GEMM2

// ------------------------------ helpers ------------------------------------
__device__ __forceinline__ uint32_t smem_u32(const void* p) {
    uint32_t a;
    asm("{ .reg .u64 t; cvta.to.shared.u64 t, %1; cvt.u32.u64 %0, t; }" : "=r"(a) : "l"(p));
    return a;
}
__device__ __forceinline__ void cpa16(uint32_t dst, const void* src) {
    asm volatile("cp.async.cg.shared.global [%0], [%1], 16;" :: "r"(dst), "l"(src));
}
__device__ __forceinline__ void cpa_commit() {
    asm volatile("cp.async.commit_group;" ::: "memory");
}
__device__ __forceinline__ void cpa_wait2() {
    asm volatile("cp.async.wait_group 2;" ::: "memory");
}
__device__ __forceinline__ void cpa_wait1() {
    asm volatile("cp.async.wait_group 1;" ::: "memory");
}
__device__ __forceinline__ void cpa_wait0() {
    asm volatile("cp.async.wait_group 0;" ::: "memory");
}
__device__ __forceinline__ void ldsm_x4(uint32_t* r, uint32_t addr) {
    asm volatile("ldmatrix.sync.aligned.m8n8.x4.shared.b16 {%0,%1,%2,%3}, [%4];"
                 : "=r"(r[0]), "=r"(r[1]), "=r"(r[2]), "=r"(r[3]) : "r"(addr));
}
// D += A * B^T via m16n8k16 fp16 inputs, fp32 accum (row.col)
__device__ __forceinline__ void mma_f16(float* c, const uint32_t* a, const uint32_t* b) {
    asm volatile(
        "mma.sync.aligned.m16n8k16.row.col.f32.f16.f16.f32 "
        "{%0,%1,%2,%3}, {%4,%5,%6,%7}, {%8,%9}, {%0,%1,%2,%3};"
        : "+f"(c[0]), "+f"(c[1]), "+f"(c[2]), "+f"(c[3])
        : "r"(a[0]), "r"(a[1]), "r"(a[2]), "r"(a[3]), "r"(b[0]), "r"(b[1]));
}

// ---------------------------------------------------------------------------
// Row L2-normalization -> fp16 scratch. grid=(NROW,2), block=256.
// ---------------------------------------------------------------------------
__global__ __launch_bounds__(256) void normalize_kernel(
    const float* __restrict__ A, const float* __restrict__ Bm)
{
    const int row   = blockIdx.x;
    const int which = blockIdx.y;
    const float* src = which ? Bm : A;
    __half*      dst = which ? g_fb : g_fa;
    const size_t base = (size_t)row * DD;

    float4 v = ((const float4*)(src + base))[threadIdx.x];
    float ss = v.x * v.x + v.y * v.y + v.z * v.z + v.w * v.w;
    #pragma unroll
    for (int o = 16; o; o >>= 1) ss += __shfl_xor_sync(0xffffffffu, ss, o);

    __shared__ float ws[8];
    if ((threadIdx.x & 31) == 0) ws[threadIdx.x >> 5] = ss;
    __syncthreads();
    float tot = 0.f;
    #pragma unroll
    for (int i = 0; i < 8; i++) tot += ws[i];

    const float inv = rsqrtf(tot) * (which ? 1.0f : 10.0f);
    __half2 h0 = __floats2half2_rn(v.x * inv, v.y * inv);
    __half2 h1 = __floats2half2_rn(v.z * inv, v.w * inv);
    uint2 pack = make_uint2(*(uint32_t*)&h0, *(uint32_t*)&h1);
    ((uint2*)(dst + base))[threadIdx.x] = pack;
}

// ---------------------------------------------------------------------------
// Fourier pos-emb TRANSPOSED: g_posT[d][p], fp16. grid=512 (omega rows).
// ---------------------------------------------------------------------------
__global__ __launch_bounds__(256) void posemb_kernel(
    const float* __restrict__ omega, const float* __restrict__ scale)
{
    const int k = blockIdx.x;                  // 0..511
    const float2 om = ((const float2*)omega)[k];
    const float s  = *scale;
    __half* rsin = g_posT + (size_t)k * HW;
    __half* rcos = g_posT + (size_t)(512 + k) * HW;

    for (int p = threadIdx.x; p < HW; p += 256) {
        const int i = p / 48, j = p % 48;
        const float gy = -1.0f + 2.0f * (float)i / 47.0f;
        const float gx = -1.0f + 2.0f * (float)j / 47.0f;
        float sn, cs;
        sincosf(s * (gx * om.x + gy * om.y), &sn, &cs);
        rsin[p] = __float2half_rn(sn);
        rcos[p] = __float2half_rn(cs);
    }
}

// ---------------------------------------------------------------------------
// fp16 mma.sync GEMM: C[M,N](f32) = A[M,K] * B[N,K]^T, batched on blockIdx.z.
// Block tile 128x256, warp tile 64x64 (8 warps, 2x4), BK=32 halves,
// 4-stage cp.async (3-ahead), ldmatrix + register double-buffering,
// kk=0 fragments primed before next-stage issue. (R14 champion, unchanged.)
// ---------------------------------------------------------------------------
#define BM 128
#define BN 256
#define BK 32
#define PADK 40                          // halves; 80B row stride, conflict-free
#define STAGE_BYTES ((BM + BN) * PADK * 2)   // 30720 B
#define NSTG 4

extern __shared__ __half smh[];

__global__ __launch_bounds__(256, 1)
void gemm_f16_kernel(const __half* __restrict__ A, const __half* __restrict__ B,
                     float* __restrict__ C,
                     int K, int lda, int ldb, int ldc,
                     size_t sA, size_t sB, size_t sC)
{
    const uint32_t sbase = smem_u32(smh);
    const int tid  = threadIdx.x;
    const int wid  = tid >> 5;
    const int lane = tid & 31;
    const int bm = blockIdx.y * BM;
    const int bn = blockIdx.x * BN;

    A += (size_t)blockIdx.z * sA;
    B += (size_t)blockIdx.z * sB;
    C += (size_t)blockIdx.z * sC;

    // ---- loader: thread owns row lr (A: 1 row, B: 2 rows), 32B (2x16B) ----
    const int lr = tid >> 1;           // 0..127
    const int lc = (tid & 1) * 16;     // halves offset: 0 or 16
    const __half* pa  = A + (size_t)(bm + lr) * lda + lc;
    const __half* pb0 = B + (size_t)(bn + lr) * ldb + lc;
    const __half* pb1 = pb0 + (size_t)128 * ldb;
    const uint32_t daa = sbase + (uint32_t)(lr * PADK + lc) * 2;
    const uint32_t db0 = sbase + BM * PADK * 2 + (uint32_t)(lr * PADK + lc) * 2;
    const uint32_t db1 = db0 + 128 * PADK * 2;

    const int nkt = K / BK;

    #define ISSUE(kt, s) do {                                     \
        const uint32_t o = (uint32_t)(s) * STAGE_BYTES;           \
        const int off = (kt) * BK;                                \
        cpa16(daa + o,      pa  + off);                           \
        cpa16(daa + o + 16, pa  + off + 8);                       \
        cpa16(db0 + o,      pb0 + off);                           \
        cpa16(db0 + o + 16, pb0 + off + 8);                       \
        cpa16(db1 + o,      pb1 + off);                           \
        cpa16(db1 + o + 16, pb1 + off + 8);                       \
        cpa_commit();                                             \
    } while (0)

    ISSUE(0, 0);
    ISSUE(1, 1);
    ISSUE(2, 2);

    // ---- compute addressing (ldmatrix lane layout) ----
    const int wm   = (wid & 1) * 64;   // warp M offset (2 rows of warps)
    const int wn   = (wid >> 1) * 64;  // warp N offset (4 cols of warps)
    const int lrow = lane & 7;
    const int msel = lane >> 3;        // matrix select 0..3
    const uint32_t aoff0 = (uint32_t)(((wm + (msel & 1) * 8 + lrow) * PADK + (msel >> 1) * 8) * 2);
    const uint32_t boff0 = (uint32_t)(((wn + (msel >> 1) * 8 + lrow) * PADK + (msel & 1) * 8) * 2)
                         + BM * PADK * 2;
    const int ga  = lane >> 2;
    const int tig = lane & 3;

    float acc[4][8][4];
    #pragma unroll
    for (int i = 0; i < 4; i++)
        #pragma unroll
        for (int j = 0; j < 8; j++)
            #pragma unroll
            for (int q = 0; q < 4; q++) acc[i][j][q] = 0.f;

    uint32_t af[2][4][4];   // [buf][am][4]
    uint32_t bf[2][4][4];   // [buf][jb][4]

    for (int kt = 0; kt < nkt; kt++) {
        const uint32_t stA = sbase + (uint32_t)(kt % NSTG) * STAGE_BYTES;
        if (kt + 2 < nkt)      cpa_wait2();
        else if (kt + 1 < nkt) cpa_wait1();
        else                   cpa_wait0();
        __syncthreads();

        // prime kk=0 fragments FIRST (MMAs start ASAP), then issue next stage
        #pragma unroll
        for (int am = 0; am < 4; am++)
            ldsm_x4(af[0][am], stA + aoff0 + am * (16 * PADK * 2));
        #pragma unroll
        for (int jb = 0; jb < 4; jb++)
            ldsm_x4(bf[0][jb], stA + boff0 + jb * (16 * PADK * 2));

        if (kt + 3 < nkt) ISSUE(kt + 3, (kt + 3) % NSTG);

        #pragma unroll
        for (int kk = 0; kk < 2; kk++) {       // BK=32 -> 2 x k16
            const int cur = kk & 1, nxt = cur ^ 1;
            if (kk < 1) {
                const uint32_t kkb = 32;       // 16 halves = 32 B
                #pragma unroll
                for (int am = 0; am < 4; am++)
                    ldsm_x4(af[nxt][am], stA + aoff0 + am * (16 * PADK * 2) + kkb);
                #pragma unroll
                for (int jb = 0; jb < 4; jb++)
                    ldsm_x4(bf[nxt][jb], stA + boff0 + jb * (16 * PADK * 2) + kkb);
            }
            #pragma unroll
            for (int am = 0; am < 4; am++) {
                #pragma unroll
                for (int jb = 0; jb < 4; jb++) {
                    mma_f16(acc[am][2 * jb],     af[cur][am], &bf[cur][jb][0]);
                    mma_f16(acc[am][2 * jb + 1], af[cur][am], &bf[cur][jb][2]);
                }
            }
        }
    }

    // ---- epilogue ----
    #pragma unroll
    for (int am = 0; am < 4; am++) {
        const int row = bm + wm + am * 16 + ga;
        #pragma unroll
        for (int an = 0; an < 8; an++) {
            const int col = bn + wn + an * 8 + tig * 2;
            float* c0 = C + (size_t)row * ldc + col;
            float* c1 = C + (size_t)(row + 8) * ldc + col;
            *(float2*)c0 = make_float2(acc[am][an][0], acc[am][an][1]);
            *(float2*)c1 = make_float2(acc[am][an][2], acc[am][an][3]);
        }
    }
    #undef ISSUE
}

// ---------------------------------------------------------------------------
// Warp-per-row max-free softmax (|logits| <= ~10.1, exp safe in fp32).
// 8 rows per 256-thread block; row lives in registers (18 float4/lane).
// No block barriers, no smem. Writes fp32 attn + fp16 copy. grid = NROW/8.
// ---------------------------------------------------------------------------
__global__ __launch_bounds__(256) void softmax_kernel(
    const float* __restrict__ logits, float* __restrict__ attn)
{
    const int wid  = threadIdx.x >> 5;
    const int lane = threadIdx.x & 31;
    const size_t row = (size_t)blockIdx.x * 8 + wid;

    const float4* src = (const float4*)(logits + row * HW);
    float4*       dst = (float4*)(attn   + row * HW);
    uint2*        dsth = (uint2*)(g_attnh + row * HW);

    float4 v[18];
    float s = 0.f;
    #pragma unroll
    for (int i = 0; i < 18; i++) {
        float4 t = src[lane + 32 * i];
        t.x = __expf(t.x); t.y = __expf(t.y);
        t.z = __expf(t.z); t.w = __expf(t.w);
        v[i] = t;
        s += t.x + t.y + t.z + t.w;
    }
    #pragma unroll
    for (int o = 16; o; o >>= 1) s += __shfl_xor_sync(0xffffffffu, s, o);
    const float inv = 1.0f / s;

    #pragma unroll
    for (int i = 0; i < 18; i++) {
        float4 t = v[i];
        t.x *= inv; t.y *= inv; t.z *= inv; t.w *= inv;
        dst[lane + 32 * i] = t;
        __half2 h0 = __floats2half2_rn(t.x, t.y);
        __half2 h1 = __floats2half2_rn(t.z, t.w);
        dsth[lane + 32 * i] = make_uint2(*(uint32_t*)&h0, *(uint32_t*)&h1);
    }
}

// ---------------------------------------------------------------------------
extern "C" void kernel_launch(void* const* d_in, const int* in_sizes, int n_in,
                              void* d_out, int out_size)
{
    const float* fA    = (const float*)d_in[0];
    const float* fB    = (const float*)d_in[1];
    const float* omega = (const float*)d_in[2];
    const float* scale = (const float*)d_in[3];

    float* out    = (float*)d_out;
    float* logits = out;
    float* attn   = out + (size_t)NB * HW * HW;
    float* match  = attn + (size_t)NB * HW * HW;

    __half *fa_p, *fb_p, *pos_p, *at_p;
    cudaGetSymbolAddress((void**)&fa_p,  g_fa);
    cudaGetSymbolAddress((void**)&fb_p,  g_fb);
    cudaGetSymbolAddress((void**)&pos_p, g_posT);
    cudaGetSymbolAddress((void**)&at_p,  g_attnh);

    const int smem_bytes = NSTG * STAGE_BYTES;   // 122880
    static bool attr_set = false;
    if (!attr_set) {
        cudaFuncSetAttribute(gemm_f16_kernel,
                             cudaFuncAttributeMaxDynamicSharedMemorySize, smem_bytes);
        attr_set = true;
    }

    normalize_kernel<<<dim3(NROW, 2), 256>>>(fA, fB);
    posemb_kernel<<<512, 256>>>(omega, scale);

    // GEMM1: logits[b] = fa[b] @ fb[b]^T   (M=HW, N=HW, K=DD)
    gemm_f16_kernel<<<dim3(HW / BN, HW / BM, NB), 256, smem_bytes>>>(
        fa_p, fb_p, logits, DD, DD, DD, HW,
        (size_t)HW * DD, (size_t)HW * DD, (size_t)HW * HW);

    softmax_kernel<<<NROW / 8, 256>>>(logits, attn);

    // GEMM2: match[b] = attn_h[b] @ posT^T   (M=HW, N=DD, K=HW)
    gemm_f16_kernel<<<dim3(DD / BN, HW / BM, NB), 256, smem_bytes>>>(
        at_p, pos_p, match, HW, HW, HW, DD,
        (size_t)HW * HW, (size_t)0, (size_t)HW * DD);
}

// round 17
// speedup vs baseline: 1.0341x; 1.0027x over previous
#include <cuda_runtime.h>
#include <cuda_fp16.h>
#include <cstdint>

#define NB   8
#define HW   2304
#define DD   1024
#define NROW (NB * HW)

// ------------------------------ scratch ------------------------------------
__device__ __half g_fa[(size_t)NROW * DD];    // normalized A, x10 = 1/TEMP
__device__ __half g_fb[(size_t)NROW * DD];    // normalized B
__device__ __half g_posT[(size_t)DD * HW];    // pos emb transposed [D][HW]
__device__ __half g_attnh[(size_t)NROW * HW]; // fp16 copy of attn for GEMM2

// ------------------------------ helpers ------------------------------------
__device__ __forceinline__ uint32_t smem_u32(const void* p) {
    uint32_t a;
    asm("{ .reg .u64 t; cvta.to.shared.u64 t, %1; cvt.u32.u64 %0, t; }" : "=r"(a) : "l"(p));
    return a;
}
__device__ __forceinline__ void cpa16(uint32_t dst, const void* src) {
    asm volatile("cp.async.cg.shared.global [%0], [%1], 16;" :: "r"(dst), "l"(src));
}
__device__ __forceinline__ void cpa_commit() {
    asm volatile("cp.async.commit_group;" ::: "memory");
}
__device__ __forceinline__ void cpa_wait2() {
    asm volatile("cp.async.wait_group 2;" ::: "memory");
}
__device__ __forceinline__ void cpa_wait1() {
    asm volatile("cp.async.wait_group 1;" ::: "memory");
}
__device__ __forceinline__ void cpa_wait0() {
    asm volatile("cp.async.wait_group 0;" ::: "memory");
}
__device__ __forceinline__ void ldsm_x4(uint32_t* r, uint32_t addr) {
    asm volatile("ldmatrix.sync.aligned.m8n8.x4.shared.b16 {%0,%1,%2,%3}, [%4];"
                 : "=r"(r[0]), "=r"(r[1]), "=r"(r[2]), "=r"(r[3]) : "r"(addr));
}
// D += A * B^T via m16n8k16 fp16 inputs, fp32 accum (row.col)
__device__ __forceinline__ void mma_f16(float* c, const uint32_t* a, const uint32_t* b) {
    asm volatile(
        "mma.sync.aligned.m16n8k16.row.col.f32.f16.f16.f32 "
        "{%0,%1,%2,%3}, {%4,%5,%6,%7}, {%8,%9}, {%0,%1,%2,%3};"
        : "+f"(c[0]), "+f"(c[1]), "+f"(c[2]), "+f"(c[3])
        : "r"(a[0]), "r"(a[1]), "r"(a[2]), "r"(a[3]), "r"(b[0]), "r"(b[1]));
}

// ---------------------------------------------------------------------------
// Row L2-normalization -> fp16 scratch. grid=(NROW,2), block=256.
// ---------------------------------------------------------------------------
__global__ __launch_bounds__(256) void normalize_kernel(
    const float* __restrict__ A, const float* __restrict__ Bm)
{
    const int row   = blockIdx.x;
    const int which = blockIdx.y;
    const float* src = which ? Bm : A;
    __half*      dst = which ? g_fb : g_fa;
    const size_t base = (size_t)row * DD;

    float4 v = ((const float4*)(src + base))[threadIdx.x];
    float ss = v.x * v.x + v.y * v.y + v.z * v.z + v.w * v.w;
    #pragma unroll
    for (int o = 16; o; o >>= 1) ss += __shfl_xor_sync(0xffffffffu, ss, o);

    __shared__ float ws[8];
    if ((threadIdx.x & 31) == 0) ws[threadIdx.x >> 5] = ss;
    __syncthreads();
    float tot = 0.f;
    #pragma unroll
    for (int i = 0; i < 8; i++) tot += ws[i];

    const float inv = rsqrtf(tot) * (which ? 1.0f : 10.0f);
    __half2 h0 = __floats2half2_rn(v.x * inv, v.y * inv);
    __half2 h1 = __floats2half2_rn(v.z * inv, v.w * inv);
    uint2 pack = make_uint2(*(uint32_t*)&h0, *(uint32_t*)&h1);
    ((uint2*)(dst + base))[threadIdx.x] = pack;
}

// ---------------------------------------------------------------------------
// Fourier pos-emb TRANSPOSED: g_posT[d][p], fp16. grid=512 (omega rows).
// ---------------------------------------------------------------------------
__global__ __launch_bounds__(256) void posemb_kernel(
    const float* __restrict__ omega, const float* __restrict__ scale)
{
    const int k = blockIdx.x;                  // 0..511
    const float2 om = ((const float2*)omega)[k];
    const float s  = *scale;
    __half* rsin = g_posT + (size_t)k * HW;
    __half* rcos = g_posT + (size_t)(512 + k) * HW;

    for (int p = threadIdx.x; p < HW; p += 256) {
        const int i = p / 48, j = p % 48;
        const float gy = -1.0f + 2.0f * (float)i / 47.0f;
        const float gx = -1.0f + 2.0f * (float)j / 47.0f;
        float sn, cs;
        sincosf(s * (gx * om.x + gy * om.y), &sn, &cs);
        rsin[p] = __float2half_rn(sn);
        rcos[p] = __float2half_rn(cs);
    }
}

// ---------------------------------------------------------------------------
// fp16 mma.sync GEMM: C[M,N](f32) = A[M,K] * B[N,K]^T, batched on blockIdx.z.
// Block tile 128x256, warp tile 64x64 (8 warps, 2x4), BK=32 halves,
// 4-stage cp.async (3-ahead), ldmatrix + register double-buffering,
// kk=0 fragments primed before next-stage issue. (R14 champion, unchanged.)
// ---------------------------------------------------------------------------
#define BM 128
#define BN 256
#define BK 32
#define PADK 40                          // halves; 80B row stride, conflict-free
#define STAGE_BYTES ((BM + BN) * PADK * 2)   // 30720 B
#define NSTG 4

extern __shared__ __half smh[];

__global__ __launch_bounds__(256, 1)
void gemm_f16_kernel(const __half* __restrict__ A, const __half* __restrict__ B,
                     float* __restrict__ C,
                     int K, int lda, int ldb, int ldc,
                     size_t sA, size_t sB, size_t sC)
{
    const uint32_t sbase = smem_u32(smh);
    const int tid  = threadIdx.x;
    const int wid  = tid >> 5;
    const int lane = tid & 31;
    const int bm = blockIdx.y * BM;
    const int bn = blockIdx.x * BN;

    A += (size_t)blockIdx.z * sA;
    B += (size_t)blockIdx.z * sB;
    C += (size_t)blockIdx.z * sC;

    // ---- loader: thread owns row lr (A: 1 row, B: 2 rows), 32B (2x16B) ----
    const int lr = tid >> 1;           // 0..127
    const int lc = (tid & 1) * 16;     // halves offset: 0 or 16
    const __half* pa  = A + (size_t)(bm + lr) * lda + lc;
    const __half* pb0 = B + (size_t)(bn + lr) * ldb + lc;
    const __half* pb1 = pb0 + (size_t)128 * ldb;
    const uint32_t daa = sbase + (uint32_t)(lr * PADK + lc) * 2;
    const uint32_t db0 = sbase + BM * PADK * 2 + (uint32_t)(lr * PADK + lc) * 2;
    const uint32_t db1 = db0 + 128 * PADK * 2;

    const int nkt = K / BK;

    #define ISSUE(kt, s) do {                                     \
        const uint32_t o = (uint32_t)(s) * STAGE_BYTES;           \
        const int off = (kt) * BK;                                \
        cpa16(daa + o,      pa  + off);                           \
        cpa16(daa + o + 16, pa  + off + 8);                       \
        cpa16(db0 + o,      pb0 + off);                           \
        cpa16(db0 + o + 16, pb0 + off + 8);                       \
        cpa16(db1 + o,      pb1 + off);                           \
        cpa16(db1 + o + 16, pb1 + off + 8);                       \
        cpa_commit();                                             \
    } while (0)

    ISSUE(0, 0);
    ISSUE(1, 1);
    ISSUE(2, 2);

    // ---- compute addressing (ldmatrix lane layout) ----
    const int wm   = (wid & 1) * 64;   // warp M offset (2 rows of warps)
    const int wn   = (wid >> 1) * 64;  // warp N offset (4 cols of warps)
    const int lrow = lane & 7;
    const int msel = lane >> 3;        // matrix select 0..3
    const uint32_t aoff0 = (uint32_t)(((wm + (msel & 1) * 8 + lrow) * PADK + (msel >> 1) * 8) * 2);
    const uint32_t boff0 = (uint32_t)(((wn + (msel >> 1) * 8 + lrow) * PADK + (msel & 1) * 8) * 2)
                         + BM * PADK * 2;
    const int ga  = lane >> 2;
    const int tig = lane & 3;

    float acc[4][8][4];
    #pragma unroll
    for (int i = 0; i < 4; i++)
        #pragma unroll
        for (int j = 0; j < 8; j++)
            #pragma unroll
            for (int q = 0; q < 4; q++) acc[i][j][q] = 0.f;

    uint32_t af[2][4][4];   // [buf][am][4]
    uint32_t bf[2][4][4];   // [buf][jb][4]

    for (int kt = 0; kt < nkt; kt++) {
        const uint32_t stA = sbase + (uint32_t)(kt % NSTG) * STAGE_BYTES;
        if (kt + 2 < nkt)      cpa_wait2();
        else if (kt + 1 < nkt) cpa_wait1();
        else                   cpa_wait0();
        __syncthreads();

        // prime kk=0 fragments FIRST (MMAs start ASAP), then issue next stage
        #pragma unroll
        for (int am = 0; am < 4; am++)
            ldsm_x4(af[0][am], stA + aoff0 + am * (16 * PADK * 2));
        #pragma unroll
        for (int jb = 0; jb < 4; jb++)
            ldsm_x4(bf[0][jb], stA + boff0 + jb * (16 * PADK * 2));

        if (kt + 3 < nkt) ISSUE(kt + 3, (kt + 3) % NSTG);

        #pragma unroll
        for (int kk = 0; kk < 2; kk++) {       // BK=32 -> 2 x k16
            const int cur = kk & 1, nxt = cur ^ 1;
            if (kk < 1) {
                const uint32_t kkb = 32;       // 16 halves = 32 B
                #pragma unroll
                for (int am = 0; am < 4; am++)
                    ldsm_x4(af[nxt][am], stA + aoff0 + am * (16 * PADK * 2) + kkb);
                #pragma unroll
                for (int jb = 0; jb < 4; jb++)
                    ldsm_x4(bf[nxt][jb], stA + boff0 + jb * (16 * PADK * 2) + kkb);
            }
            #pragma unroll
            for (int am = 0; am < 4; am++) {
                #pragma unroll
                for (int jb = 0; jb < 4; jb++) {
                    mma_f16(acc[am][2 * jb],     af[cur][am], &bf[cur][jb][0]);
                    mma_f16(acc[am][2 * jb + 1], af[cur][am], &bf[cur][jb][2]);
                }
            }
        }
    }

    // ---- epilogue ----
    #pragma unroll
    for (int am = 0; am < 4; am++) {
        const int row = bm + wm + am * 16 + ga;
        #pragma unroll
        for (int an = 0; an < 8; an++) {
            const int col = bn + wn + an * 8 + tig * 2;
            float* c0 = C + (size_t)row * ldc + col;
            float* c1 = C + (size_t)(row + 8) * ldc + col;
            *(float2*)c0 = make_float2(acc[am][an][0], acc[am][an][1]);
            *(float2*)c1 = make_float2(acc[am][an][2], acc[am][an][3]);
        }
    }
    #undef ISSUE
}

// ---------------------------------------------------------------------------
// Warp-per-row max-free softmax, fp16-compressed row registers.
// 8 rows per 256-thread block; exps held as 36 half2 regs (vs 72 fp32).
// No block barriers, no smem. Writes fp32 attn + fp16 copy. grid = NROW/8.
// ---------------------------------------------------------------------------
__global__ __launch_bounds__(256) void softmax_kernel(
    const float* __restrict__ logits, float* __restrict__ attn)
{
    const int wid  = threadIdx.x >> 5;
    const int lane = threadIdx.x & 31;
    const size_t row = (size_t)blockIdx.x * 8 + wid;

    const float4* src = (const float4*)(logits + row * HW);
    float4*       dst = (float4*)(attn   + row * HW);
    uint2*        dsth = (uint2*)(g_attnh + row * HW);

    uint2 e[18];                         // packed half2 exps (36 regs)
    float s = 0.f;
    #pragma unroll
    for (int i = 0; i < 18; i++) {
        float4 t = src[lane + 32 * i];
        t.x = __expf(t.x); t.y = __expf(t.y);
        t.z = __expf(t.z); t.w = __expf(t.w);
        s += t.x + t.y + t.z + t.w;
        __half2 h0 = __floats2half2_rn(t.x, t.y);
        __half2 h1 = __floats2half2_rn(t.z, t.w);
        e[i] = make_uint2(*(uint32_t*)&h0, *(uint32_t*)&h1);
    }
    #pragma unroll
    for (int o = 16; o; o >>= 1) s += __shfl_xor_sync(0xffffffffu, s, o);
    const float inv = 1.0f / s;

    #pragma unroll
    for (int i = 0; i < 18; i++) {
        const float2 f0 = __half22float2(*(const __half2*)&e[i].x);
        const float2 f1 = __half22float2(*(const __half2*)&e[i].y);
        dst[lane + 32 * i] = make_float4(f0.x * inv, f0.y * inv, f1.x * inv, f1.y * inv);
        __half2 h0 = __floats2half2_rn(f0.x * inv, f0.y * inv);
        __half2 h1 = __floats2half2_rn(f1.x * inv, f1.y * inv);
        dsth[lane + 32 * i] = make_uint2(*(uint32_t*)&h0, *(uint32_t*)&h1);
    }
}

// ---------------------------------------------------------------------------
extern "C" void kernel_launch(void* const* d_in, const int* in_sizes, int n_in,
                              void* d_out, int out_size)
{
    const float* fA    = (const float*)d_in[0];
    const float* fB    = (const float*)d_in[1];
    const float* omega = (const float*)d_in[2];
    const float* scale = (const float*)d_in[3];

    float* out    = (float*)d_out;
    float* logits = out;
    float* attn   = out + (size_t)NB * HW * HW;
    float* match  = attn + (size_t)NB * HW * HW;

    __half *fa_p, *fb_p, *pos_p, *at_p;
    cudaGetSymbolAddress((void**)&fa_p,  g_fa);
    cudaGetSymbolAddress((void**)&fb_p,  g_fb);
    cudaGetSymbolAddress((void**)&pos_p, g_posT);
    cudaGetSymbolAddress((void**)&at_p,  g_attnh);

    const int smem_bytes = NSTG * STAGE_BYTES;   // 122880
    static bool attr_set = false;
    if (!attr_set) {
        cudaFuncSetAttribute(gemm_f16_kernel,
                             cudaFuncAttributeMaxDynamicSharedMemorySize, smem_bytes);
        attr_set = true;
    }

    normalize_kernel<<<dim3(NROW, 2), 256>>>(fA, fB);
    posemb_kernel<<<512, 256>>>(omega, scale);

    // GEMM1: logits[b] = fa[b] @ fb[b]^T   (M=HW, N=HW, K=DD)
    gemm_f16_kernel<<<dim3(HW / BN, HW / BM, NB), 256, smem_bytes>>>(
        fa_p, fb_p, logits, DD, DD, DD, HW,
        (size_t)HW * DD, (size_t)HW * DD, (size_t)HW * HW);

    softmax_kernel<<<NROW / 8, 256>>>(logits, attn);

    // GEMM2: match[b] = attn_h[b] @ posT^T   (M=HW, N=DD, K=HW)
    gemm_f16_kernel<<<dim3(DD / BN, HW / BM, NB), 256, smem_bytes>>>(
        at_p, pos_p, match, HW, HW, HW, DD,
        (size_t)HW * HW, (size_t)0, (size_t)HW * DD);
}